// round 13
// baseline (speedup 1.0000x reference)
#include <cuda_runtime.h>
#include <cuda_fp16.h>
#include <cstdint>

#define B_ 4
#define N_ 4096
#define F_ 64
#define BM 64
#define BK 32
#define NKT (N_ / BK)                  // 128

// unified 2-stage ring: [A fp32 swizzled 3x64x128B][T fp16 3x64x64B]
#define A_CH_B (BM * 128)              // 8192
#define A_ST_B (3 * A_CH_B)            // 24576
#define T_CH_B (F_ * 64)               // 4096
#define T_OFF A_ST_B
#define STAGE_BYTES (A_ST_B + 3 * T_CH_B)   // 36864
#define SMEM_BYTES (2 * STAGE_BYTES)   // 73728 -> 3 CTAs/SM

// T scratch: g_T[c][b][n][k] = fp16_rne( (X[b] @ w_c)[k][n] )
__device__ __half g_T[3][B_][F_][N_];

// ---------------------------------------------------------------------------
__device__ __forceinline__ uint32_t smem_u32(const void* p) {
    uint32_t a;
    asm("{ .reg .u64 t; cvta.to.shared.u64 t, %1; cvt.u32.u64 %0, t; }"
        : "=r"(a) : "l"(p));
    return a;
}
__device__ __forceinline__ void ldsm4(uint32_t* r, uint32_t addr) {
    asm volatile("ldmatrix.sync.aligned.m8n8.x4.shared.b16 {%0,%1,%2,%3}, [%4];"
                 : "=r"(r[0]), "=r"(r[1]), "=r"(r[2]), "=r"(r[3]) : "r"(addr));
}
__device__ __forceinline__ uint32_t lds_cvt(uint32_t addr) {
    float x, y;
    asm volatile("ld.shared.v2.f32 {%0,%1}, [%2];" : "=f"(x), "=f"(y) : "r"(addr));
    __half2 h = __floats2half2_rn(x, y);
    return *(uint32_t*)&h;
}
__device__ __forceinline__ void mma16816(float* d, const uint32_t* a,
                                         uint32_t b0, uint32_t b1) {
    asm volatile("mma.sync.aligned.m16n8k16.row.col.f32.f16.f16.f32 "
                 "{%0,%1,%2,%3}, {%4,%5,%6,%7}, {%8,%9}, {%0,%1,%2,%3};"
                 : "+f"(d[0]), "+f"(d[1]), "+f"(d[2]), "+f"(d[3])
                 : "r"(a[0]), "r"(a[1]), "r"(a[2]), "r"(a[3]), "r"(b0), "r"(b1));
}
__device__ __forceinline__ uint32_t packh2(float x, float y) {
    __half2 h = __floats2half2_rn(x, y);
    return *(uint32_t*)&h;
}

// ---------------------------------------------------------------------------
// Kernel 1: g_T[c][b][g][m] = fp16( sum_f X[b][m][f] * w_c[f][g] )
// ---------------------------------------------------------------------------
__global__ void __launch_bounds__(256)
compute_T_kernel(const float* __restrict__ X,
                 const float* __restrict__ w0,
                 const float* __restrict__ w1,
                 const float* __restrict__ w2) {
    const int c = blockIdx.z;
    const int b = blockIdx.y;
    const int m0 = blockIdx.x * 64;
    const float* w = (c == 0) ? w0 : (c == 1) ? w1 : w2;

    __shared__ float sX[64 * 68];
    __shared__ float sW[64 * 68];

    const int tid = threadIdx.x;
    {
        const int q = tid & 15;
        const int r = tid >> 4;
        #pragma unroll
        for (int j = 0; j < 4; j++) {
            const int row = r + 16 * j;
            *(float4*)(sX + row * 68 + q * 4) =
                *(const float4*)(X + ((size_t)b * N_ + m0 + row) * F_ + q * 4);
            *(float4*)(sW + row * 68 + q * 4) =
                *(const float4*)(w + (size_t)row * F_ + q * 4);
        }
    }
    __syncthreads();

    const int row = tid & 63;
    const int g0  = (tid >> 6) * 16;

    float acc[16];
    #pragma unroll
    for (int i = 0; i < 16; i++) acc[i] = 0.f;

    #pragma unroll 8
    for (int f = 0; f < 64; f++) {
        const float x = sX[row * 68 + f];
        #pragma unroll
        for (int j = 0; j < 4; j++) {
            float4 wv = *(const float4*)(sW + f * 68 + g0 + j * 4);
            acc[j * 4 + 0] += x * wv.x;
            acc[j * 4 + 1] += x * wv.y;
            acc[j * 4 + 2] += x * wv.z;
            acc[j * 4 + 3] += x * wv.w;
        }
    }
    __syncthreads();

    #pragma unroll
    for (int j = 0; j < 4; j++)
        *(float4*)(sX + row * 68 + g0 + j * 4) =
            make_float4(acc[j*4+0], acc[j*4+1], acc[j*4+2], acc[j*4+3]);
    __syncthreads();

    const int g  = tid >> 2;
    const int ms = (tid & 3) * 16;
    uint32_t h[8];
    #pragma unroll
    for (int i = 0; i < 8; i++)
        h[i] = packh2(sX[(ms + 2*i) * 68 + g], sX[(ms + 2*i + 1) * 68 + g]);
    __half* out = &g_T[c][b][g][m0 + ms];
    ((uint4*)out)[0] = make_uint4(h[0], h[1], h[2], h[3]);
    ((uint4*)out)[1] = make_uint4(h[4], h[5], h[6], h[7]);
}

// ---------------------------------------------------------------------------
// Kernel 2: Y[b] = relu(A0@T0 + A1@T1 + A2@T2)
// grid (64, 4) = 256 CTAs, block 128 (4 warps, warp tile 16x64), 3 CTAs/SM.
// Pure cp.async 2-stage ring (A fp32 swizzled + T fp16), two barriers/iter:
//   wait+sync -> compute(stage s) -> sync -> refill slot s&1 with k-tile s+2.
// Cross-CTA overlap (12 warps/SM) hides per-CTA waits and barriers.
// ---------------------------------------------------------------------------
__global__ void __launch_bounds__(128, 3)
gnn_main_kernel(const float* __restrict__ A0,
                const float* __restrict__ A1,
                const float* __restrict__ A2,
                float* __restrict__ Y) {
    extern __shared__ char smem[];
    const uint32_t sb = smem_u32(smem);
    const int tid = threadIdx.x;
    const int b = blockIdx.y;
    const int rowBase = blockIdx.x * BM;
    const int lane = tid & 31;
    const int warp = tid >> 5;

    const float* Abase[3];
    Abase[0] = A0 + (size_t)b * N_ * N_;
    Abase[1] = A1 + (size_t)b * N_ * N_;
    Abase[2] = A2 + (size_t)b * N_ * N_;

    // A cp.async map: 12 x 16B per thread (192 rows x 8 chunks, XOR swizzle)
    const float* aSrc[12];
    uint32_t aDst[12];
    #pragma unroll
    for (int j = 0; j < 12; j++) {
        const int id  = tid + 128 * j;          // 0..1535
        const int row = id >> 3;                // 0..191 (chain*64 + r)
        const int ch  = id & 7;                 // 16B chunk within 128B row
        const int c   = row >> 6;
        const int r   = row & 63;
        aSrc[j] = Abase[c] + (size_t)(rowBase + r) * N_ + ch * 4;
        aDst[j] = (uint32_t)(row * 128 + 16 * (ch ^ ((r >> 1) & 3)));
    }
    // T cp.async map: 6 x 16B per thread
    const __half* tSrc[6];
    uint32_t tDst[6];
    #pragma unroll
    for (int j = 0; j < 6; j++) {
        const int id = tid + 128 * j;           // 0..767
        const int c  = id >> 8;
        const int n  = (id >> 2) & 63;
        const int ch = id & 3;
        tSrc[j] = &g_T[c][b][n][0] + ch * 8;
        tDst[j] = (uint32_t)(T_OFF + c * T_CH_B + n * 64
                             + 16 * (ch ^ ((n >> 1) & 3)));
    }

    #define CP_STAGE(kt, slot) do {                                            \
        const uint32_t _so = sb + (uint32_t)(slot) * STAGE_BYTES;              \
        const int _k0 = (kt) * BK;                                             \
        _Pragma("unroll")                                                      \
        for (int j = 0; j < 12; j++)                                           \
            asm volatile("cp.async.cg.shared.global [%0], [%1], 16;"           \
                         :: "r"(_so + aDst[j]), "l"(aSrc[j] + _k0) : "memory");\
        _Pragma("unroll")                                                      \
        for (int j = 0; j < 6; j++)                                            \
            asm volatile("cp.async.cg.shared.global [%0], [%1], 16;"           \
                         :: "r"(_so + tDst[j]), "l"(tSrc[j] + _k0) : "memory");\
        asm volatile("cp.async.commit_group;" ::: "memory");                   \
    } while (0)

    // fragment geometry: 4 warps, warp tile 16(M) x 64(N)
    const int mrow = lane >> 2;        // 0..7
    const int kp   = lane & 3;
    const int row16 = lane & 15;
    const int cbit  = lane >> 4;
    const uint32_t swzB = (uint32_t)((row16 >> 1) & 3);
    const uint32_t swzA = (uint32_t)((mrow >> 1) & 3);
    const uint32_t aRow0 = (uint32_t)((warp * 16 + mrow) * 128);
    const uint32_t bRowOff = (uint32_t)(T_OFF + row16 * 64);

    float acc[8][4];
    #pragma unroll
    for (int nt = 0; nt < 8; nt++)
        #pragma unroll
        for (int i = 0; i < 4; i++) acc[nt][i] = 0.f;

    // prologue: both stages in flight
    CP_STAGE(0, 0);
    CP_STAGE(1, 1);

    for (int s = 0; s < NKT; s++) {
        const int slot = s & 1;
        // stage s complete (committed groups: 0..s+1; allow s+1 pending)
        asm volatile("cp.async.wait_group 1;" ::: "memory");
        __syncthreads();

        const uint32_t stBase = sb + (uint32_t)slot * STAGE_BYTES;
        #pragma unroll
        for (int c = 0; c < 3; c++) {
            const uint32_t aCh = stBase + c * A_CH_B + aRow0;
            const uint32_t bCh = stBase + c * T_CH_B + bRowOff;
            #pragma unroll
            for (int ks = 0; ks < 2; ks++) {
                const uint32_t c0 = (uint32_t)(ks * 4 + (kp >> 1));
                const uint32_t o0 = 16u * (c0 ^ swzA) + (uint32_t)((kp & 1) * 8);
                const uint32_t o2 = 16u * ((c0 + 2) ^ swzA) + (uint32_t)((kp & 1) * 8);
                uint32_t a[4];
                a[0] = lds_cvt(aCh + o0);
                a[1] = lds_cvt(aCh + 1024 + o0);   // +8 rows
                a[2] = lds_cvt(aCh + o2);
                a[3] = lds_cvt(aCh + 1024 + o2);
                const uint32_t kch = 16u * ((uint32_t)((ks << 1) | cbit) ^ swzB);
                #pragma unroll
                for (int nt = 0; nt < 4; nt++) {
                    uint32_t bb[4];
                    ldsm4(bb, bCh + nt * 1024 + kch);
                    mma16816(acc[2*nt],     a, bb[0], bb[2]);
                    mma16816(acc[2*nt + 1], a, bb[1], bb[3]);
                }
            }
        }

        // all warps done reading slot s&1 before it is overwritten
        __syncthreads();
        if (s + 2 < NKT) {
            CP_STAGE(s + 2, slot);
        } else {
            asm volatile("cp.async.commit_group;" ::: "memory");
        }
    }

    // epilogue: relu + store
    #pragma unroll
    for (int nt = 0; nt < 8; nt++) {
        const int rr  = rowBase + warp * 16 + (lane >> 2);
        const int col = nt * 8 + (lane & 3) * 2;
        float2 v0 = make_float2(fmaxf(acc[nt][0], 0.f), fmaxf(acc[nt][1], 0.f));
        float2 v1 = make_float2(fmaxf(acc[nt][2], 0.f), fmaxf(acc[nt][3], 0.f));
        *(float2*)(Y + ((size_t)b * N_ + rr) * F_ + col)     = v0;
        *(float2*)(Y + ((size_t)b * N_ + rr + 8) * F_ + col) = v1;
    }
}

// ---------------------------------------------------------------------------
extern "C" void kernel_launch(void* const* d_in, const int* in_sizes, int n_in,
                              void* d_out, int out_size) {
    (void)in_sizes; (void)n_in; (void)out_size;
    const float* X  = (const float*)d_in[0];
    const float* A0 = (const float*)d_in[1];
    const float* A1 = (const float*)d_in[2];
    const float* A2 = (const float*)d_in[3];
    const float* w0 = (const float*)d_in[4];
    const float* w1 = (const float*)d_in[5];
    const float* w2 = (const float*)d_in[6];
    float* Y = (float*)d_out;

    dim3 g1(N_ / 64, B_, 3);
    compute_T_kernel<<<g1, 256>>>(X, w0, w1, w2);

    cudaFuncSetAttribute(gnn_main_kernel,
                         cudaFuncAttributeMaxDynamicSharedMemorySize, SMEM_BYTES);
    dim3 g2(N_ / BM, B_);
    gnn_main_kernel<<<g2, 128, SMEM_BYTES>>>(A0, A1, A2, Y);
}

// round 14
// speedup vs baseline: 1.8585x; 1.8585x over previous
#include <cuda_runtime.h>
#include <cuda_fp16.h>
#include <cstdint>

#define B_ 4
#define N_ 4096
#define F_ 64
#define BM 128
#define BK 32
#define NKT (N_ / BK)                  // 128
#define STAGES 3

// stage layout: A fp32 (3 chains x 128 rows x 160B padded) + T fp16 (3 x 64 x 64B)
#define A_ROW_B 160
#define A_CH_B (BM * A_ROW_B)          // 20480
#define A_BYTES (3 * A_CH_B)           // 61440
#define T_CH_B (F_ * 64)               // 4096
#define T_OFF A_BYTES
#define STAGE_BYTES (A_BYTES + 3 * T_CH_B)   // 73728
#define SMEM_BYTES (STAGES * STAGE_BYTES)    // 221184

// T scratch: g_T[c][b][n][k] = fp16_rne( (X[b] @ w_c)[k][n] )
__device__ __half g_T[3][B_][F_][N_];

// ---------------------------------------------------------------------------
__device__ __forceinline__ uint32_t smem_u32(const void* p) {
    uint32_t a;
    asm("{ .reg .u64 t; cvta.to.shared.u64 t, %1; cvt.u32.u64 %0, t; }"
        : "=r"(a) : "l"(p));
    return a;
}
__device__ __forceinline__ void ldsm4(uint32_t* r, uint32_t addr) {
    asm volatile("ldmatrix.sync.aligned.m8n8.x4.shared.b16 {%0,%1,%2,%3}, [%4];"
                 : "=r"(r[0]), "=r"(r[1]), "=r"(r[2]), "=r"(r[3]) : "r"(addr));
}
__device__ __forceinline__ uint32_t lds_cvt(uint32_t addr) {
    float x, y;
    asm volatile("ld.shared.v2.f32 {%0,%1}, [%2];" : "=f"(x), "=f"(y) : "r"(addr));
    __half2 h = __floats2half2_rn(x, y);
    return *(uint32_t*)&h;
}
__device__ __forceinline__ void mma16816(float* d, const uint32_t* a,
                                         uint32_t b0, uint32_t b1) {
    asm volatile("mma.sync.aligned.m16n8k16.row.col.f32.f16.f16.f32 "
                 "{%0,%1,%2,%3}, {%4,%5,%6,%7}, {%8,%9}, {%0,%1,%2,%3};"
                 : "+f"(d[0]), "+f"(d[1]), "+f"(d[2]), "+f"(d[3])
                 : "r"(a[0]), "r"(a[1]), "r"(a[2]), "r"(a[3]), "r"(b0), "r"(b1));
}
__device__ __forceinline__ uint32_t packh2(float x, float y) {
    __half2 h = __floats2half2_rn(x, y);
    return *(uint32_t*)&h;
}

// ---------------------------------------------------------------------------
// Kernel 1: g_T[c][b][g][m] = fp16( sum_f X[b][m][f] * w_c[f][g] )
// (sW reads warp-broadcast: all lanes of a warp share g0)
// ---------------------------------------------------------------------------
__global__ void __launch_bounds__(256)
compute_T_kernel(const float* __restrict__ X,
                 const float* __restrict__ w0,
                 const float* __restrict__ w1,
                 const float* __restrict__ w2) {
    const int c = blockIdx.z;
    const int b = blockIdx.y;
    const int m0 = blockIdx.x * 64;
    const float* w = (c == 0) ? w0 : (c == 1) ? w1 : w2;

    __shared__ float sX[64 * 68];
    __shared__ float sW[64 * 68];

    const int tid = threadIdx.x;
    {
        const int q = tid & 15;
        const int r = tid >> 4;
        #pragma unroll
        for (int j = 0; j < 4; j++) {
            const int row = r + 16 * j;
            *(float4*)(sX + row * 68 + q * 4) =
                *(const float4*)(X + ((size_t)b * N_ + m0 + row) * F_ + q * 4);
            *(float4*)(sW + row * 68 + q * 4) =
                *(const float4*)(w + (size_t)row * F_ + q * 4);
        }
    }
    __syncthreads();

    const int row = tid & 63;            // distinct per lane -> 1 wavefront
    const int g0  = (tid >> 6) * 16;     // uniform per warp -> broadcast

    float acc[16];
    #pragma unroll
    for (int i = 0; i < 16; i++) acc[i] = 0.f;

    #pragma unroll 8
    for (int f = 0; f < 64; f++) {
        const float x = sX[row * 68 + f];
        #pragma unroll
        for (int j = 0; j < 4; j++) {
            float4 wv = *(const float4*)(sW + f * 68 + g0 + j * 4);
            acc[j * 4 + 0] += x * wv.x;
            acc[j * 4 + 1] += x * wv.y;
            acc[j * 4 + 2] += x * wv.z;
            acc[j * 4 + 3] += x * wv.w;
        }
    }
    __syncthreads();

    #pragma unroll
    for (int j = 0; j < 4; j++)
        *(float4*)(sX + row * 68 + g0 + j * 4) =
            make_float4(acc[j*4+0], acc[j*4+1], acc[j*4+2], acc[j*4+3]);
    __syncthreads();

    const int g  = tid >> 2;
    const int ms = (tid & 3) * 16;
    uint32_t h[8];
    #pragma unroll
    for (int i = 0; i < 8; i++)
        h[i] = packh2(sX[(ms + 2*i) * 68 + g], sX[(ms + 2*i + 1) * 68 + g]);
    __half* out = &g_T[c][b][g][m0 + ms];
    ((uint4*)out)[0] = make_uint4(h[0], h[1], h[2], h[3]);
    ((uint4*)out)[1] = make_uint4(h[4], h[5], h[6], h[7]);
}

// ---------------------------------------------------------------------------
// Kernel 2: Y[b] = relu(A0@T0 + A1@T1 + A2@T2)   [R6 geometry, refill-at-top]
// grid (32, 4) = 128 CTAs, block 256 (8 warps, warp tile 16x64).
// Pure cp.async 3-stage ring: A fp32 (160B padded rows) + T fp16 (ldmatrix).
// Loop: wait_group 1 -> sync -> refill slot s+2 (read at iter s-1; safe) ->
//       compute stage s. Single barrier per iteration.
// ---------------------------------------------------------------------------
__global__ void __launch_bounds__(256, 1)
gnn_main_kernel(const float* __restrict__ A0,
                const float* __restrict__ A1,
                const float* __restrict__ A2,
                float* __restrict__ Y) {
    extern __shared__ char smem[];
    const uint32_t sb = smem_u32(smem);
    const int tid = threadIdx.x;
    const int b = blockIdx.y;
    const int rowBase = blockIdx.x * BM;

    const float* Ap[3];
    Ap[0] = A0 + (size_t)b * N_ * N_;
    Ap[1] = A1 + (size_t)b * N_ * N_;
    Ap[2] = A2 + (size_t)b * N_ * N_;

    // A cp.async map: 12 x 16B per thread (384 rows x 8 chunks)
    const float* aSrc[12];
    uint32_t aDst[12];
    #pragma unroll
    for (int j = 0; j < 12; j++) {
        const int id  = tid + 256 * j;          // 0..3071
        const int row = id >> 3;                // 0..383 (chain*128 + r)
        const int ch  = id & 7;                 // 16B chunk within 128B row
        const int c   = row >> 7;
        const int r   = row & 127;
        aSrc[j] = Ap[c] + (size_t)(rowBase + r) * N_ + ch * 4;
        aDst[j] = (uint32_t)(row * A_ROW_B + ch * 16);
    }
    // T cp.async map: 3 x 16B per thread
    const __half* tSrc[3];
    uint32_t tDst[3];
    #pragma unroll
    for (int j = 0; j < 3; j++) {
        const int id = tid + 256 * j;           // 0..767
        const int c  = id >> 8;
        const int n  = (id >> 2) & 63;
        const int ch = id & 3;
        tSrc[j] = &g_T[c][b][n][0] + ch * 8;
        tDst[j] = (uint32_t)(T_OFF + c * T_CH_B + n * 64
                             + 16 * (ch ^ ((n >> 1) & 3)));
    }

    #define CP_STAGE(kt, slot) do {                                            \
        const uint32_t _so = sb + (uint32_t)(slot) * STAGE_BYTES;              \
        const int _k0 = (kt) * BK;                                             \
        _Pragma("unroll")                                                      \
        for (int j = 0; j < 12; j++)                                           \
            asm volatile("cp.async.cg.shared.global [%0], [%1], 16;"           \
                         :: "r"(_so + aDst[j]), "l"(aSrc[j] + _k0) : "memory");\
        _Pragma("unroll")                                                      \
        for (int j = 0; j < 3; j++)                                            \
            asm volatile("cp.async.cg.shared.global [%0], [%1], 16;"           \
                         :: "r"(_so + tDst[j]), "l"(tSrc[j] + _k0) : "memory");\
        asm volatile("cp.async.commit_group;" ::: "memory");                   \
    } while (0)

    // fragment geometry: 8 warps, warp tile 16(M) x 64(N)
    const int lane = tid & 31;
    const int warp = tid >> 5;
    const int mrow = lane >> 2;        // 0..7
    const int kp   = lane & 3;         // k-pair index
    const int row16 = lane & 15;
    const int cbit  = lane >> 4;
    const uint32_t swz = (uint32_t)((row16 >> 1) & 3);
    const uint32_t aFragOff = (uint32_t)((warp * 16 + mrow) * A_ROW_B + kp * 8);
    const uint32_t bRowOff  = (uint32_t)(T_OFF + row16 * 64);

    float acc[8][4];
    #pragma unroll
    for (int nt = 0; nt < 8; nt++)
        #pragma unroll
        for (int i = 0; i < 4; i++) acc[nt][i] = 0.f;

    // prologue: stages 0,1 in flight
    CP_STAGE(0, 0);
    CP_STAGE(1, 1);

    for (int s = 0; s < NKT; s++) {
        const int slot = s % 3;
        asm volatile("cp.async.wait_group 1;" ::: "memory");
        __syncthreads();

        // refill slot (s+2)%3 FIRST: it was last read at iter s-1 and all
        // warps passed the barrier above after those reads — race-free.
        // Issuing before compute gives the fill a full extra compute phase.
        if (s + 2 < NKT) {
            CP_STAGE(s + 2, (s + 2) % 3);
        } else {
            asm volatile("cp.async.commit_group;" ::: "memory");
        }

        const uint32_t stBase = sb + (uint32_t)slot * STAGE_BYTES;
        #pragma unroll
        for (int c = 0; c < 3; c++) {
            const uint32_t aCh = stBase + c * A_CH_B + aFragOff;
            const uint32_t bCh = stBase + c * T_CH_B + bRowOff;
            #pragma unroll
            for (int ks = 0; ks < 2; ks++) {
                // A fragment m16k16 (fp32 -> fp16 in-register)
                uint32_t a[4];
                const uint32_t ak = aCh + ks * 64;
                a[0] = lds_cvt(ak);
                a[1] = lds_cvt(ak + 8 * A_ROW_B);
                a[2] = lds_cvt(ak + 32);
                a[3] = lds_cvt(ak + 8 * A_ROW_B + 32);
                const uint32_t kch = 16u * ((uint32_t)((ks << 1) | cbit) ^ swz);
                #pragma unroll
                for (int nt = 0; nt < 4; nt++) {
                    uint32_t bb[4];
                    ldsm4(bb, bCh + nt * 1024 + kch);
                    mma16816(acc[2*nt],     a, bb[0], bb[2]);
                    mma16816(acc[2*nt + 1], a, bb[1], bb[3]);
                }
            }
        }
    }

    // epilogue: relu + store
    #pragma unroll
    for (int nt = 0; nt < 8; nt++) {
        const int r0  = rowBase + warp * 16 + (lane >> 2);
        const int col = nt * 8 + (lane & 3) * 2;
        float2 v0 = make_float2(fmaxf(acc[nt][0], 0.f), fmaxf(acc[nt][1], 0.f));
        float2 v1 = make_float2(fmaxf(acc[nt][2], 0.f), fmaxf(acc[nt][3], 0.f));
        *(float2*)(Y + ((size_t)b * N_ + r0) * F_ + col)     = v0;
        *(float2*)(Y + ((size_t)b * N_ + r0 + 8) * F_ + col) = v1;
    }
}

// ---------------------------------------------------------------------------
extern "C" void kernel_launch(void* const* d_in, const int* in_sizes, int n_in,
                              void* d_out, int out_size) {
    (void)in_sizes; (void)n_in; (void)out_size;
    const float* X  = (const float*)d_in[0];
    const float* A0 = (const float*)d_in[1];
    const float* A1 = (const float*)d_in[2];
    const float* A2 = (const float*)d_in[3];
    const float* w0 = (const float*)d_in[4];
    const float* w1 = (const float*)d_in[5];
    const float* w2 = (const float*)d_in[6];
    float* Y = (float*)d_out;

    dim3 g1(N_ / 64, B_, 3);
    compute_T_kernel<<<g1, 256>>>(X, w0, w1, w2);

    cudaFuncSetAttribute(gnn_main_kernel,
                         cudaFuncAttributeMaxDynamicSharedMemorySize, SMEM_BYTES);
    dim3 g2(N_ / BM, B_);
    gnn_main_kernel<<<g2, 256, SMEM_BYTES>>>(A0, A1, A2, Y);
}